// round 16
// baseline (speedup 1.0000x reference)
#include <cuda_runtime.h>
#include <cuda_bf16.h>
#include <cstdint>

// ============ sizes ============
// B=512, D=512, L=256, 2 layers. Persistent: 128 blocks x 256 thr, 1/SM.
// block (m0=bid>>5, n0=bid&31): 128 batch rows x 16 d (= 64 packed gate rows).
// Packed gate-row order within block: r = wn*32 + gate*8 + dr
//   -> warp wn's 32 N-cols = {i,f,g,o} x 8 d's  (epilogue stays in registers).

// smem layout (bytes)
static constexpr int SMEM_BYTES = 229376;
static constexpr int W1_OFF = 65536;    // W0: [0,65536)  64 rows x 1024B
static constexpr int AB_OFF = 196608;   // W1: [65536,196608) 64 rows x 2048B
                                        // A:  [196608,229376) 2 x 16KB chunks

// ============ device scratch ============
__device__ __nv_bfloat16 g_h0[2][512 * 512];
__device__ __nv_bfloat16 g_A1[2][512 * 1024];   // [y0 | h1]
__device__ float g_c0[512 * 512];
__device__ float g_c1[512 * 512];
__device__ unsigned short g_W0p[32 * 64 * 512];
__device__ unsigned short g_W1p[32 * 64 * 1024];
__device__ float g_b0p[2048];
__device__ float g_b1p[2048];
__device__ float g_Opart[256 * 64 * 512];
__device__ unsigned g_syncA[128];               // per-m0 counters (padded)

__device__ __forceinline__ float tanhax(float x) {
    float r;
    asm("tanh.approx.f32 %0, %1;" : "=f"(r) : "f"(x));
    return r;
}
__device__ __forceinline__ float sigax(float x) {
    return fmaf(tanhax(0.5f * x), 0.5f, 0.5f);
}
__device__ __forceinline__ void cpa16(unsigned dst_s, const void* src_g) {
    asm volatile("cp.async.cg.shared.global [%0], [%1], 16;" :: "r"(dst_s), "l"(src_g));
}
__device__ __forceinline__ void mma_bf16(float* c, const unsigned* a,
                                         unsigned b0, unsigned b1) {
    asm volatile(
        "mma.sync.aligned.m16n8k16.row.col.f32.bf16.bf16.f32 "
        "{%0,%1,%2,%3},{%4,%5,%6,%7},{%8,%9},{%0,%1,%2,%3};"
        : "+f"(c[0]), "+f"(c[1]), "+f"(c[2]), "+f"(c[3])
        : "r"(a[0]), "r"(a[1]), "r"(a[2]), "r"(a[3]), "r"(b0), "r"(b1));
}
__device__ __forceinline__ void ldsm4(unsigned* r, unsigned addr) {
    asm volatile("ldmatrix.sync.aligned.m8n8.x4.shared.b16 {%0,%1,%2,%3}, [%4];"
                 : "=r"(r[0]), "=r"(r[1]), "=r"(r[2]), "=r"(r[3]) : "r"(addr));
}

// ============ weight pack: bf16 + gate-interleaved layout + XOR swizzle ============
// packed row r (0..63): wn=r>>5, gate q=(r>>3)&3, dr=r&7
//   orig gate row = q*512 + n*16 + wn*8 + dr.
// bf16 pair-word w (k>>1) stored at w ^ ((r&7)<<2)  == 16B seg (k>>3)^(r&7).
__global__ void pack_weights(const float* __restrict__ Whh0,
                             const float* __restrict__ Wih1,
                             const float* __restrict__ Whh1,
                             const float* __restrict__ bih0,
                             const float* __restrict__ bhh0,
                             const float* __restrict__ bih1,
                             const float* __restrict__ bhh1) {
    int idx = blockIdx.x * blockDim.x + threadIdx.x;
    const int T0 = 32 * 64 * 512;
    const int T1 = 32 * 64 * 1024;
    if (idx < T0) {
        int k = idx & 511, r = (idx >> 9) & 63, n = idx >> 15;
        int orow = ((r >> 3) & 3) * 512 + n * 16 + (r >> 5) * 8 + (r & 7);
        int w = (k >> 1) ^ ((r & 7) << 2);
        __nv_bfloat16 v = __float2bfloat16(Whh0[orow * 512 + k]);
        g_W0p[(n * 64 + r) * 512 + w * 2 + (k & 1)] =
            *reinterpret_cast<unsigned short*>(&v);
    } else if (idx < T0 + T1) {
        int i2 = idx - T0;
        int k = i2 & 1023, r = (i2 >> 10) & 63, n = i2 >> 16;
        int orow = ((r >> 3) & 3) * 512 + n * 16 + (r >> 5) * 8 + (r & 7);
        float f = (k < 512) ? Wih1[orow * 512 + k] : Whh1[orow * 512 + (k - 512)];
        int w = (k >> 1) ^ ((r & 7) << 2);
        __nv_bfloat16 v = __float2bfloat16(f);
        g_W1p[(n * 64 + r) * 1024 + w * 2 + (k & 1)] =
            *reinterpret_cast<unsigned short*>(&v);
    } else if (idx < T0 + T1 + 2048) {
        int j = idx - T0 - T1;
        int n = j >> 6, r = j & 63;
        int orow = ((r >> 3) & 3) * 512 + n * 16 + (r >> 5) * 8 + (r & 7);
        g_b0p[j] = bih0[orow] + bhh0[orow];
        g_b1p[j] = bih1[orow] + bhh1[orow];
    }
}

// ============ init: tanh(c_star @ W^T + b), interleaved reshape ============
__global__ void __launch_bounds__(256) init_gemm(const float* __restrict__ cstar,
                                                 const float* __restrict__ Wt,
                                                 const float* __restrict__ bias,
                                                 int is_h) {
    __shared__ float As[64][20];
    __shared__ float Bs[64][20];
    int tid = threadIdx.x;
    int rb0 = blockIdx.x * 64, n0 = blockIdx.y * 64;
    int tx = tid & 15, ty = tid >> 4;
    float acc[4][4];
#pragma unroll
    for (int i = 0; i < 4; i++)
#pragma unroll
        for (int j = 0; j < 4; j++) acc[i][j] = 0.f;
    int lr = tid >> 2, lc = (tid & 3) * 4;
    for (int k0 = 0; k0 < 512; k0 += 16) {
        *(float4*)&As[lr][lc] = *(const float4*)&cstar[(rb0 + lr) * 512 + k0 + lc];
        *(float4*)&Bs[lr][lc] = *(const float4*)&Wt[(n0 + lr) * 512 + k0 + lc];
        __syncthreads();
#pragma unroll
        for (int kk = 0; kk < 16; kk++) {
            float a[4], bv[4];
#pragma unroll
            for (int i = 0; i < 4; i++) a[i] = As[ty + 16 * i][kk];
#pragma unroll
            for (int j = 0; j < 4; j++) bv[j] = Bs[tx + 16 * j][kk];
#pragma unroll
            for (int i = 0; i < 4; i++)
#pragma unroll
                for (int j = 0; j < 4; j++) acc[i][j] += a[i] * bv[j];
        }
        __syncthreads();
    }
#pragma unroll
    for (int i = 0; i < 4; i++)
#pragma unroll
        for (int j = 0; j < 4; j++) {
            int rb = rb0 + ty + 16 * i;
            int n = n0 + tx + 16 * j;
            float v = tanhf(acc[i][j] + bias[n]);
            int b = ((rb & 255) << 1) + (n >> 9);
            int d = n & 511;
            if (is_h) {
                if (rb < 256) g_h0[0][b * 512 + d] = __float2bfloat16(v);
                else          g_A1[0][b * 1024 + 512 + d] = __float2bfloat16(v);
            } else {
                if (rb < 256) g_c0[b * 512 + d] = v;
                else          g_c1[b * 512 + d] = v;
            }
        }
}

__global__ void reset_sync() {
    if (threadIdx.x < 128) g_syncA[threadIdx.x] = 0;
}

// ============ persistent recurrence ============
__global__ void __launch_bounds__(256, 1) lstm_persist(const float* __restrict__ ow_g) {
    extern __shared__ char smem_c[];
    const int tid = threadIdx.x, lane = tid & 31, wid = tid >> 5;
    const int bid = blockIdx.x;
    const int m0 = bid >> 5, n0 = bid & 31;
    const int wm = wid & 3, wn = wid >> 2;
    unsigned smem_u = (unsigned)__cvta_generic_to_shared(smem_c);
    const unsigned ab_u = smem_u + AB_OFF;

    // ---- stage this block's weight slices (already packed+swizzled) ----
    {
        const unsigned short* s0 = g_W0p + n0 * (64 * 512);
        for (int i = tid; i < 4096; i += 256) cpa16(smem_u + i * 16, s0 + i * 8);
        const unsigned short* s1 = g_W1p + n0 * (64 * 1024);
        for (int i = tid; i < 8192; i += 256) cpa16(smem_u + W1_OFF + i * 16, s1 + i * 8);
        asm volatile("cp.async.commit_group;");
        asm volatile("cp.async.wait_group 0;");
        __syncthreads();
    }

    // ---- per-thread epilogue geometry (fragment-resident) ----
    const int gp = lane >> 2, tg = lane & 3;
    const int dloc = wn * 8 + tg * 2;        // local d of this thread's pair
    const int dg = n0 * 16 + dloc;           // global d
    // rows owned: wm*32 + mf*16 + rr*8 + gp   (mf,rr in 0..1)

    float c0r[8], c1r[8], br0[4][2], br1[4][2], owr[2];
#pragma unroll
    for (int q = 0; q < 4; q++)
#pragma unroll
        for (int e = 0; e < 2; e++) {
            br0[q][e] = g_b0p[n0 * 64 + wn * 32 + q * 8 + tg * 2 + e];
            br1[q][e] = g_b1p[n0 * 64 + wn * 32 + q * 8 + tg * 2 + e];
        }
    owr[0] = ow_g[dg];
    owr[1] = ow_g[dg + 1];
#pragma unroll
    for (int mf = 0; mf < 2; mf++)
#pragma unroll
        for (int rr = 0; rr < 2; rr++) {
            int b = m0 * 128 + wm * 32 + mf * 16 + rr * 8 + gp;
#pragma unroll
            for (int e = 0; e < 2; e++) {
                c0r[mf * 4 + rr * 2 + e] = g_c0[b * 512 + dg + e];
                c1r[mf * 4 + rr * 2 + e] = g_c1[b * 512 + dg + e];
            }
        }

    // ---- ldsm lane geometry (as validated in R14) ----
    const int l7 = lane & 7;
    const int aR0 = wm * 32 + l7 + ((lane >> 3) & 1) * 8;
    const int aKs = lane >> 4;
    const int bR0 = wn * 32 + l7 + (lane >> 4) * 8;
    const int bKs = (lane >> 3) & 1;

    // ---- chunk loader (s-seg fixed per thread) ----
    const int sseg = tid & 7;
    const int rbase = tid >> 3;
    const unsigned swz = (unsigned)((sseg ^ (rbase & 7)) << 4);
    unsigned gc = 0;

    auto issueLoad = [&](const __nv_bfloat16* __restrict__ src, int K, int kc) {
        unsigned dst = ab_u + (gc & 1) * 16384;
        const __nv_bfloat16* s = src + (size_t)(m0 * 128 + rbase) * K + kc * 64 + sseg * 8;
#pragma unroll
        for (int i = 0; i < 4; i++) {
            cpa16(dst + (rbase + i * 32) * 128 + swz, s + (size_t)i * 32 * K);
        }
        asm volatile("cp.async.commit_group;");
        gc++;
    };

    auto gsync = [&](unsigned target) {
        __threadfence();
        __syncthreads();
        if (tid == 0) {
            atomicAdd(&g_syncA[m0 * 32], 1u);
            unsigned v;
            do {
                asm volatile("ld.acquire.gpu.global.u32 %0, [%1];"
                             : "=r"(v) : "l"(&g_syncA[m0 * 32]));
            } while (v < target);
        }
        __syncthreads();
    };

    // ---- fragment epilogue ----
    auto epi = [&](int t, float* cr, const float (&br)[4][2], bool isL1,
                   float (&acc)[2][4][4]) {
#pragma unroll
        for (int mf = 0; mf < 2; mf++)
#pragma unroll
            for (int rr = 0; rr < 2; rr++) {
                int b = m0 * 128 + wm * 32 + mf * 16 + rr * 8 + gp;
                float part = 0.f;
                unsigned short hv[2];
#pragma unroll
                for (int e = 0; e < 2; e++) {
                    float iv = acc[mf][0][rr * 2 + e] + br[0][e];
                    float fv = acc[mf][1][rr * 2 + e] + br[1][e];
                    float gv = acc[mf][2][rr * 2 + e] + br[2][e];
                    float ov = acc[mf][3][rr * 2 + e] + br[3][e];
                    int ci = mf * 4 + rr * 2 + e;
                    float cn = sigax(fv) * cr[ci] + sigax(iv) * tanhax(gv);
                    float hn = sigax(ov) * tanhax(cn);
                    cr[ci] = cn;
                    __nv_bfloat16 hb = __float2bfloat16(hn);
                    hv[e] = *reinterpret_cast<unsigned short*>(&hb);
                    if (isL1) part += hn * owr[e];
                }
                unsigned pk = (unsigned)hv[0] | ((unsigned)hv[1] << 16);
                if (!isL1) {
                    *(unsigned*)&g_h0[(t + 1) & 1][b * 512 + dg] = pk;
                    *(unsigned*)&g_A1[t & 1][b * 1024 + dg] = pk;
                } else {
                    *(unsigned*)&g_A1[(t + 1) & 1][b * 1024 + 512 + dg] = pk;
                    part += __shfl_xor_sync(0xffffffffu, part, 1);
                    part += __shfl_xor_sync(0xffffffffu, part, 2);
                    if (tg == 0)
                        g_Opart[((t * 32 + n0) * 2 + wn) * 512 + b] = part;
                }
            }
    };

    // ---- main loop: phase p = layer0(t=p) + layer1(t=p-1), merged pipeline ----
    float accA[2][4][4], accB[2][4][4];
    for (int p = 0; p <= 256; p++) {
        const bool do0 = p < 256, do1 = p >= 1;
        const __nv_bfloat16* A0 = g_h0[p & 1];
        const __nv_bfloat16* A1s = g_A1[(p - 1) & 1];
        const int NC0 = do0 ? 8 : 0;
        const int NCt = NC0 + (do1 ? 16 : 0);

#pragma unroll
        for (int i = 0; i < 2; i++)
#pragma unroll
            for (int j = 0; j < 4; j++)
#pragma unroll
                for (int x = 0; x < 4; x++) { accA[i][j][x] = 0.f; accB[i][j][x] = 0.f; }

        const unsigned gs = gc;
        // chunk 0 load
        if (NC0) issueLoad(A0, 512, 0);
        else     issueLoad(A1s, 1024, 0);

        for (int c = 0; c < NCt; c++) {
            asm volatile("cp.async.wait_group 0;");
            __syncthreads();
            if (c + 1 < NCt) {
                if (c + 1 < NC0) issueLoad(A0, 512, c + 1);
                else             issueLoad(A1s, 1024, c + 1 - NC0);
            }
            const bool is0 = c < NC0;
            const int kcw = is0 ? c : c - NC0;
            const unsigned abase = ab_u + ((gs + c) & 1) * 16384;
            const unsigned wbase = is0 ? smem_u : (smem_u + W1_OFF);
            const int RB = is0 ? 1024 : 2048;
            float (&acc)[2][4][4] = is0 ? accA : accB;
#pragma unroll
            for (int ks = 0; ks < 4; ks++) {
                unsigned a0[4], a1[4], bA[4], bB[4];
                {
                    int r = aR0;
                    ldsm4(a0, abase + r * 128 + (((ks * 2 + aKs) ^ (r & 7)) << 4));
                    r = aR0 + 16;
                    ldsm4(a1, abase + r * 128 + (((ks * 2 + aKs) ^ (r & 7)) << 4));
                    int kg = kcw * 8 + ks * 2 + bKs;
                    r = bR0;
                    ldsm4(bA, wbase + r * RB + ((kg ^ (r & 7)) << 4));
                    r = bR0 + 16;
                    ldsm4(bB, wbase + r * RB + ((kg ^ (r & 7)) << 4));
                }
                mma_bf16(acc[0][0], a0, bA[0], bA[1]);
                mma_bf16(acc[1][0], a1, bA[0], bA[1]);
                mma_bf16(acc[0][1], a0, bA[2], bA[3]);
                mma_bf16(acc[1][1], a1, bA[2], bA[3]);
                mma_bf16(acc[0][2], a0, bB[0], bB[1]);
                mma_bf16(acc[1][2], a1, bB[0], bB[1]);
                mma_bf16(acc[0][3], a0, bB[2], bB[3]);
                mma_bf16(acc[1][3], a1, bB[2], bB[3]);
            }
        }

        if (do0) epi(p, c0r, br0, false, accA);
        if (do1) epi(p - 1, c1r, br1, true, accB);
        gsync((unsigned)(p + 1) * 32u);
    }
}

// ============ final projection reduce + layout ============
__global__ void final_proj(const float* __restrict__ out_b, float* __restrict__ out) {
    int idx = blockIdx.x * blockDim.x + threadIdx.x;
    if (idx >= 512 * 256) return;
    int t = idx >> 9, b = idx & 511;
    float s = out_b[0];
#pragma unroll
    for (int j = 0; j < 64; j++) s += g_Opart[(t * 64 + j) * 512 + b];
    if (t < 255) out[b * 255 + t] = s;     // recon (B, L-1)
    else         out[512 * 255 + b] = s;   // pred (B,)
}

// ============ launch ============
extern "C" void kernel_launch(void* const* d_in, const int* in_sizes, int n_in,
                              void* d_out, int out_size) {
    (void)in_sizes; (void)n_in; (void)out_size;
    const float* c_star   = (const float*)d_in[0];
    const float* init_h_w = (const float*)d_in[1];
    const float* init_h_b = (const float*)d_in[2];
    const float* init_c_w = (const float*)d_in[3];
    const float* init_c_b = (const float*)d_in[4];
    // d_in[5] = W_ih0: unused (layer0 input term is pure bias)
    const float* W_hh0 = (const float*)d_in[6];
    const float* b_ih0 = (const float*)d_in[7];
    const float* b_hh0 = (const float*)d_in[8];
    const float* W_ih1 = (const float*)d_in[9];
    const float* W_hh1 = (const float*)d_in[10];
    const float* b_ih1 = (const float*)d_in[11];
    const float* b_hh1 = (const float*)d_in[12];
    const float* out_w = (const float*)d_in[13];
    const float* out_b = (const float*)d_in[14];
    float* out = (float*)d_out;

    static bool attr_set = false;
    if (!attr_set) {
        cudaFuncSetAttribute(lstm_persist,
                             cudaFuncAttributeMaxDynamicSharedMemorySize, SMEM_BYTES);
        attr_set = true;
    }

    pack_weights<<<12296, 256>>>(W_hh0, W_ih1, W_hh1, b_ih0, b_hh0, b_ih1, b_hh1);
    dim3 ig(8, 16);
    init_gemm<<<ig, 256>>>(c_star, init_h_w, init_h_b, 1);
    init_gemm<<<ig, 256>>>(c_star, init_c_w, init_c_b, 0);
    reset_sync<<<1, 128>>>();
    lstm_persist<<<128, 256, SMEM_BYTES>>>(out_w);
    final_proj<<<512, 256>>>(out_b, out);
}

// round 17
// speedup vs baseline: 1.6700x; 1.6700x over previous
#include <cuda_runtime.h>
#include <cuda_bf16.h>
#include <cstdint>

// ============ sizes ============
// B=512, D=512, L=256, 2 layers. Persistent: 128 blocks x 256 thr, 1/SM.
// block (m0=bid>>5, n0=bid&31): 128 batch rows x 16 d (= 64 packed gate rows).
// Packed gate-row order: r = wn*32 + gate*8 + dr  -> warp wn's 32 N-cols hold
// all 4 gates for d = n0*16 + wn*8 + dr  (epilogue stays in registers).

// smem layout (bytes)
static constexpr int SMEM_BYTES = 229376;
static constexpr int W1_OFF = 65536;    // W0: [0,65536)  64 rows x 1024B
static constexpr int AB_OFF = 196608;   // W1: [65536,196608) 64 rows x 2048B
                                        // A:  [196608,229376) 2 x 16KB chunks

// ============ device scratch ============
__device__ __nv_bfloat16 g_h0[2][512 * 512];
__device__ __nv_bfloat16 g_A1[2][512 * 1024];   // [y0 | h1]
__device__ float g_c0[512 * 512];
__device__ float g_c1[512 * 512];
__device__ unsigned short g_W0p[32 * 64 * 512];
__device__ unsigned short g_W1p[32 * 64 * 1024];
__device__ float g_b0p[2048];
__device__ float g_b1p[2048];
__device__ float g_Opart[256 * 64 * 512];
__device__ unsigned g_syncA[128];               // per-m0 counters (padded: m0*32)

__device__ __forceinline__ float tanhax(float x) {
    float r;
    asm("tanh.approx.f32 %0, %1;" : "=f"(r) : "f"(x));
    return r;
}
__device__ __forceinline__ float sigax(float x) {
    return fmaf(tanhax(0.5f * x), 0.5f, 0.5f);
}
__device__ __forceinline__ void cpa16(unsigned dst_s, const void* src_g) {
    asm volatile("cp.async.cg.shared.global [%0], [%1], 16;" :: "r"(dst_s), "l"(src_g));
}
__device__ __forceinline__ void mma_bf16(float* c, const unsigned* a,
                                         unsigned b0, unsigned b1) {
    asm volatile(
        "mma.sync.aligned.m16n8k16.row.col.f32.bf16.bf16.f32 "
        "{%0,%1,%2,%3},{%4,%5,%6,%7},{%8,%9},{%0,%1,%2,%3};"
        : "+f"(c[0]), "+f"(c[1]), "+f"(c[2]), "+f"(c[3])
        : "r"(a[0]), "r"(a[1]), "r"(a[2]), "r"(a[3]), "r"(b0), "r"(b1));
}
__device__ __forceinline__ void ldsm4(unsigned* r, unsigned addr) {
    asm volatile("ldmatrix.sync.aligned.m8n8.x4.shared.b16 {%0,%1,%2,%3}, [%4];"
                 : "=r"(r[0]), "=r"(r[1]), "=r"(r[2]), "=r"(r[3]) : "r"(addr));
}

// ============ weight pack: bf16 + gate-interleaved layout + XOR swizzle ============
// packed row r (0..63): wn=r>>5, gate q=(r>>3)&3, dr=r&7
//   orig gate row = q*512 + n*16 + wn*8 + dr.
// bf16 pair-word w (k>>1) stored at w ^ ((r&7)<<2)  == 16B seg (k>>3)^(r&7).
__global__ void pack_weights(const float* __restrict__ Whh0,
                             const float* __restrict__ Wih1,
                             const float* __restrict__ Whh1,
                             const float* __restrict__ bih0,
                             const float* __restrict__ bhh0,
                             const float* __restrict__ bih1,
                             const float* __restrict__ bhh1) {
    int idx = blockIdx.x * blockDim.x + threadIdx.x;
    const int T0 = 32 * 64 * 512;
    const int T1 = 32 * 64 * 1024;
    if (idx < T0) {
        int k = idx & 511, r = (idx >> 9) & 63, n = idx >> 15;
        int orow = ((r >> 3) & 3) * 512 + n * 16 + (r >> 5) * 8 + (r & 7);
        int w = (k >> 1) ^ ((r & 7) << 2);
        __nv_bfloat16 v = __float2bfloat16(Whh0[orow * 512 + k]);
        g_W0p[(n * 64 + r) * 512 + w * 2 + (k & 1)] =
            *reinterpret_cast<unsigned short*>(&v);
    } else if (idx < T0 + T1) {
        int i2 = idx - T0;
        int k = i2 & 1023, r = (i2 >> 10) & 63, n = i2 >> 16;
        int orow = ((r >> 3) & 3) * 512 + n * 16 + (r >> 5) * 8 + (r & 7);
        float f = (k < 512) ? Wih1[orow * 512 + k] : Whh1[orow * 512 + (k - 512)];
        int w = (k >> 1) ^ ((r & 7) << 2);
        __nv_bfloat16 v = __float2bfloat16(f);
        g_W1p[(n * 64 + r) * 1024 + w * 2 + (k & 1)] =
            *reinterpret_cast<unsigned short*>(&v);
    } else if (idx < T0 + T1 + 2048) {
        int j = idx - T0 - T1;
        int n = j >> 6, r = j & 63;
        int orow = ((r >> 3) & 3) * 512 + n * 16 + (r >> 5) * 8 + (r & 7);
        g_b0p[j] = bih0[orow] + bhh0[orow];
        g_b1p[j] = bih1[orow] + bhh1[orow];
    }
}

// ============ init: tanh(c_star @ W^T + b), interleaved reshape ============
__global__ void __launch_bounds__(256) init_gemm(const float* __restrict__ cstar,
                                                 const float* __restrict__ Wt,
                                                 const float* __restrict__ bias,
                                                 int is_h) {
    __shared__ float As[64][20];
    __shared__ float Bs[64][20];
    int tid = threadIdx.x;
    int rb0 = blockIdx.x * 64, n0 = blockIdx.y * 64;
    int tx = tid & 15, ty = tid >> 4;
    float acc[4][4];
#pragma unroll
    for (int i = 0; i < 4; i++)
#pragma unroll
        for (int j = 0; j < 4; j++) acc[i][j] = 0.f;
    int lr = tid >> 2, lc = (tid & 3) * 4;
    for (int k0 = 0; k0 < 512; k0 += 16) {
        *(float4*)&As[lr][lc] = *(const float4*)&cstar[(rb0 + lr) * 512 + k0 + lc];
        *(float4*)&Bs[lr][lc] = *(const float4*)&Wt[(n0 + lr) * 512 + k0 + lc];
        __syncthreads();
#pragma unroll
        for (int kk = 0; kk < 16; kk++) {
            float a[4], bv[4];
#pragma unroll
            for (int i = 0; i < 4; i++) a[i] = As[ty + 16 * i][kk];
#pragma unroll
            for (int j = 0; j < 4; j++) bv[j] = Bs[tx + 16 * j][kk];
#pragma unroll
            for (int i = 0; i < 4; i++)
#pragma unroll
                for (int j = 0; j < 4; j++) acc[i][j] += a[i] * bv[j];
        }
        __syncthreads();
    }
#pragma unroll
    for (int i = 0; i < 4; i++)
#pragma unroll
        for (int j = 0; j < 4; j++) {
            int rb = rb0 + ty + 16 * i;
            int n = n0 + tx + 16 * j;
            float v = tanhf(acc[i][j] + bias[n]);
            int b = ((rb & 255) << 1) + (n >> 9);
            int d = n & 511;
            if (is_h) {
                if (rb < 256) g_h0[0][b * 512 + d] = __float2bfloat16(v);
                else          g_A1[0][b * 1024 + 512 + d] = __float2bfloat16(v);
            } else {
                if (rb < 256) g_c0[b * 512 + d] = v;
                else          g_c1[b * 512 + d] = v;
            }
        }
}

__global__ void reset_sync() {
    if (threadIdx.x < 128) g_syncA[threadIdx.x] = 0;
}

// ============ persistent recurrence ============
__global__ void __launch_bounds__(256, 1) lstm_persist(const float* __restrict__ ow_g) {
    extern __shared__ char smem_c[];
    const int tid = threadIdx.x, lane = tid & 31, wid = tid >> 5;
    const int bid = blockIdx.x;
    const int m0 = bid >> 5, n0 = bid & 31;
    const int wm = wid & 3, wn = wid >> 2;
    unsigned smem_u = (unsigned)__cvta_generic_to_shared(smem_c);
    const unsigned ab_u = smem_u + AB_OFF;

    // ---- stage this block's weight slices (already packed+swizzled) ----
    {
        const unsigned short* s0 = g_W0p + n0 * (64 * 512);
        for (int i = tid; i < 4096; i += 256) cpa16(smem_u + i * 16, s0 + i * 8);
        const unsigned short* s1 = g_W1p + n0 * (64 * 1024);
        for (int i = tid; i < 8192; i += 256) cpa16(smem_u + W1_OFF + i * 16, s1 + i * 8);
        asm volatile("cp.async.commit_group;");
        asm volatile("cp.async.wait_group 0;");
        __syncthreads();
    }

    // ---- per-thread epilogue geometry (fragment-resident, validated R16) ----
    const int gp = lane >> 2, tg = lane & 3;
    const int dg = n0 * 16 + wn * 8 + tg * 2;   // this thread's global d pair

    float c0r[8], c1r[8], br0[4][2], br1[4][2], owr[2];
#pragma unroll
    for (int q = 0; q < 4; q++)
#pragma unroll
        for (int e = 0; e < 2; e++) {
            br0[q][e] = g_b0p[n0 * 64 + wn * 32 + q * 8 + tg * 2 + e];
            br1[q][e] = g_b1p[n0 * 64 + wn * 32 + q * 8 + tg * 2 + e];
        }
    owr[0] = ow_g[dg];
    owr[1] = ow_g[dg + 1];
#pragma unroll
    for (int mf = 0; mf < 2; mf++)
#pragma unroll
        for (int rr = 0; rr < 2; rr++) {
            int b = m0 * 128 + wm * 32 + mf * 16 + rr * 8 + gp;
#pragma unroll
            for (int e = 0; e < 2; e++) {
                c0r[mf * 4 + rr * 2 + e] = g_c0[b * 512 + dg + e];
                c1r[mf * 4 + rr * 2 + e] = g_c1[b * 512 + dg + e];
            }
        }

    // ---- ldsm lane geometry (validated R14) ----
    const int l7 = lane & 7;
    const int aR0 = wm * 32 + l7 + ((lane >> 3) & 1) * 8;
    const int aKs = lane >> 4;
    const int bR0 = wn * 32 + l7 + (lane >> 4) * 8;
    const int bKs = (lane >> 3) & 1;

    // ---- A-chunk loader ----
    const int sseg = tid & 7;
    const int rbase = tid >> 3;
    const unsigned swz = (unsigned)((sseg ^ (rbase & 7)) << 4);
    unsigned gc = 0;

    auto issueLoad = [&](const __nv_bfloat16* __restrict__ src, int K, int kc) {
        unsigned dst = ab_u + (gc & 1) * 16384;
        const __nv_bfloat16* s =
            src + (size_t)(m0 * 128 + rbase) * K + kc * 64 + sseg * 8;
#pragma unroll
        for (int i = 0; i < 4; i++)
            cpa16(dst + (rbase + i * 32) * 128 + swz, s + (size_t)i * 32 * K);
        asm volatile("cp.async.commit_group;");
        gc++;
    };

    auto gsync = [&](unsigned target) {
        __threadfence();
        __syncthreads();
        if (tid == 0) {
            atomicAdd(&g_syncA[m0 * 32], 1u);
            unsigned v;
            do {
                asm volatile("ld.acquire.gpu.global.u32 %0, [%1];"
                             : "=r"(v) : "l"(&g_syncA[m0 * 32]));
            } while (v < target);
        }
        __syncthreads();
    };

    float acc[2][4][4];  // single static accumulator bank (no dynamic refs!)

    // GEMM: acc = A[128xK] @ W[64xK]^T ; R14-proven pipeline. pre: chunk0 in flight.
    auto run_gemm = [&](const __nv_bfloat16* __restrict__ Ag, int K, unsigned wbase,
                        int RB, bool pre) {
        const int NC = K >> 6;
        const unsigned gs = gc - (pre ? 1u : 0u);
#pragma unroll
        for (int i = 0; i < 2; i++)
#pragma unroll
            for (int j = 0; j < 4; j++)
#pragma unroll
                for (int x = 0; x < 4; x++) acc[i][j][x] = 0.f;
        if (!pre) issueLoad(Ag, K, 0);
        for (int kc = 0; kc < NC; kc++) {
            if (kc + 1 < NC) {
                issueLoad(Ag, K, kc + 1);
                asm volatile("cp.async.wait_group 1;");
            } else {
                asm volatile("cp.async.wait_group 0;");
            }
            __syncthreads();
            const unsigned abase = ab_u + ((gs + kc) & 1) * 16384;
#pragma unroll
            for (int ks = 0; ks < 4; ks++) {
                unsigned a0[4], a1[4], bA[4], bB[4];
                {
                    int r = aR0;
                    ldsm4(a0, abase + r * 128 + (((ks * 2 + aKs) ^ (r & 7)) << 4));
                    r = aR0 + 16;
                    ldsm4(a1, abase + r * 128 + (((ks * 2 + aKs) ^ (r & 7)) << 4));
                    int kg = kc * 8 + ks * 2 + bKs;
                    r = bR0;
                    ldsm4(bA, wbase + r * RB + ((kg ^ (r & 7)) << 4));
                    r = bR0 + 16;
                    ldsm4(bB, wbase + r * RB + ((kg ^ (r & 7)) << 4));
                }
                mma_bf16(acc[0][0], a0, bA[0], bA[1]);
                mma_bf16(acc[1][0], a1, bA[0], bA[1]);
                mma_bf16(acc[0][1], a0, bA[2], bA[3]);
                mma_bf16(acc[1][1], a1, bA[2], bA[3]);
                mma_bf16(acc[0][2], a0, bB[0], bB[1]);
                mma_bf16(acc[1][2], a1, bB[0], bB[1]);
                mma_bf16(acc[0][3], a0, bB[2], bB[3]);
                mma_bf16(acc[1][3], a1, bB[2], bB[3]);
            }
            __syncthreads();
        }
    };

    // fragment-resident LSTM epilogue (register-only; validated R16)
    auto epi = [&](int t, float* cr, const float (&br)[4][2], bool isL1) {
#pragma unroll
        for (int mf = 0; mf < 2; mf++)
#pragma unroll
            for (int rr = 0; rr < 2; rr++) {
                int b = m0 * 128 + wm * 32 + mf * 16 + rr * 8 + gp;
                float part = 0.f;
                unsigned short hv[2];
#pragma unroll
                for (int e = 0; e < 2; e++) {
                    float iv = acc[mf][0][rr * 2 + e] + br[0][e];
                    float fv = acc[mf][1][rr * 2 + e] + br[1][e];
                    float gv = acc[mf][2][rr * 2 + e] + br[2][e];
                    float ov = acc[mf][3][rr * 2 + e] + br[3][e];
                    int ci = mf * 4 + rr * 2 + e;
                    float cn = sigax(fv) * cr[ci] + sigax(iv) * tanhax(gv);
                    float hn = sigax(ov) * tanhax(cn);
                    cr[ci] = cn;
                    __nv_bfloat16 hb = __float2bfloat16(hn);
                    hv[e] = *reinterpret_cast<unsigned short*>(&hb);
                    if (isL1) part += hn * owr[e];
                }
                unsigned pk = (unsigned)hv[0] | ((unsigned)hv[1] << 16);
                if (!isL1) {
                    *(unsigned*)&g_h0[(t + 1) & 1][b * 512 + dg] = pk;
                    *(unsigned*)&g_A1[t & 1][b * 1024 + dg] = pk;
                } else {
                    *(unsigned*)&g_A1[(t + 1) & 1][b * 1024 + 512 + dg] = pk;
                    part += __shfl_xor_sync(0xffffffffu, part, 1);
                    part += __shfl_xor_sync(0xffffffffu, part, 2);
                    if (tg == 0)
                        g_Opart[((t * 32 + n0) * 2 + wn) * 512 + b] = part;
                }
            }
    };

    // ---- phase p: layer0(t=p) for p<256 ; layer1(t=p-1) for p>=1 ----
    for (int p = 0; p <= 256; p++) {
        const bool do0 = p < 256, do1 = p >= 1;
        const __nv_bfloat16* A1s = g_A1[(p - 1) & 1];
        if (do0) {
            run_gemm(g_h0[p & 1], 512, smem_u, 1024, false);
            if (do1) issueLoad(A1s, 1024, 0);  // prefetch G1 chunk0 under epilogue
            epi(p, c0r, br0, false);
        }
        if (do1) {
            run_gemm(A1s, 1024, smem_u + W1_OFF, 2048, do0);
            epi(p - 1, c1r, br1, true);
        }
        gsync((unsigned)(p + 1) * 32u);
    }
}

// ============ final projection reduce + layout ============
__global__ void final_proj(const float* __restrict__ out_b, float* __restrict__ out) {
    int idx = blockIdx.x * blockDim.x + threadIdx.x;
    if (idx >= 512 * 256) return;
    int t = idx >> 9, b = idx & 511;
    float s = out_b[0];
#pragma unroll
    for (int j = 0; j < 64; j++) s += g_Opart[(t * 64 + j) * 512 + b];
    if (t < 255) out[b * 255 + t] = s;     // recon (B, L-1)
    else         out[512 * 255 + b] = s;   // pred (B,)
}

// ============ launch ============
extern "C" void kernel_launch(void* const* d_in, const int* in_sizes, int n_in,
                              void* d_out, int out_size) {
    (void)in_sizes; (void)n_in; (void)out_size;
    const float* c_star   = (const float*)d_in[0];
    const float* init_h_w = (const float*)d_in[1];
    const float* init_h_b = (const float*)d_in[2];
    const float* init_c_w = (const float*)d_in[3];
    const float* init_c_b = (const float*)d_in[4];
    // d_in[5] = W_ih0: unused (layer0 input term is pure bias)
    const float* W_hh0 = (const float*)d_in[6];
    const float* b_ih0 = (const float*)d_in[7];
    const float* b_hh0 = (const float*)d_in[8];
    const float* W_ih1 = (const float*)d_in[9];
    const float* W_hh1 = (const float*)d_in[10];
    const float* b_ih1 = (const float*)d_in[11];
    const float* b_hh1 = (const float*)d_in[12];
    const float* out_w = (const float*)d_in[13];
    const float* out_b = (const float*)d_in[14];
    float* out = (float*)d_out;

    static bool attr_set = false;
    if (!attr_set) {
        cudaFuncSetAttribute(lstm_persist,
                             cudaFuncAttributeMaxDynamicSharedMemorySize, SMEM_BYTES);
        attr_set = true;
    }

    pack_weights<<<12296, 256>>>(W_hh0, W_ih1, W_hh1, b_ih0, b_hh0, b_ih1, b_hh1);
    dim3 ig(8, 16);
    init_gemm<<<ig, 256>>>(c_star, init_h_w, init_h_b, 1);
    init_gemm<<<ig, 256>>>(c_star, init_c_w, init_c_b, 0);
    reset_sync<<<1, 128>>>();
    lstm_persist<<<128, 256, SMEM_BYTES>>>(out_w);
    final_proj<<<512, 256>>>(out_b, out);
}